// round 10
// baseline (speedup 1.0000x reference)
#include <cuda_runtime.h>
#include <cuda_bf16.h>
#include <math.h>

#define NBINS 32
#define TILE  128
#define NT    256
#define GBLK  592          // 148 SMs * 4 resident blocks
#define RQ    9            // smem row stride in float4 (8 data quads + 1 pad)
#define NCELL (NBINS * NBINS)

// ---------------- scratch (no allocations allowed) ----------------
__device__ unsigned g_minbits;
__device__ unsigned g_maxbits;
__device__ float    g_part[NCELL * GBLK];   // [cell][block] fp32 partials (~2.4 MB)
__device__ double   g_pab[NCELL];           // fp64 joint histogram sums

// order-preserving encoding so uint atomicMin/Max give exact float min/max
__device__ __forceinline__ unsigned enc_f(float v) {
    unsigned u = __float_as_uint(v);
    return (u & 0x80000000u) ? ~u : (u | 0x80000000u);
}
__device__ __forceinline__ float dec_f(unsigned u) {
    return (u & 0x80000000u) ? __uint_as_float(u & 0x7FFFFFFFu)
                             : __uint_as_float(~u);
}

// packed fp32x2 FMA: each half is an exact IEEE fp32 FMA (bit-identical to fmaf)
__device__ __forceinline__ void ffma2(unsigned long long& d,
                                      unsigned long long a,
                                      unsigned long long b) {
    asm("fma.rn.f32x2 %0, %1, %2, %0;" : "+l"(d) : "l"(a), "l"(b));
}
__device__ __forceinline__ unsigned long long dup_f32(float v) {
    unsigned long long r;
    asm("mov.b64 %0, {%1, %1};" : "=l"(r) : "r"(__float_as_uint(v)));
    return r;
}

__global__ void mi_init() {
    g_minbits = 0xFFFFFFFFu;
    g_maxbits = 0u;
}

// no-op probe: keeps mi_main at global launch index 5 so ncu (-s 5 -c 1)
// captures the hot kernel instead of mi_reduce.
__global__ void mi_probe() {}

__global__ void mi_minmax(const float* __restrict__ p,
                          const float* __restrict__ t, int N) {
    unsigned lmin = 0xFFFFFFFFu, lmax = 0u;
    int stride = gridDim.x * blockDim.x;
    int gtid = blockIdx.x * blockDim.x + threadIdx.x;
    int n4 = N >> 2;
    const float4* p4 = (const float4*)p;
    const float4* t4 = (const float4*)t;
    for (int i = gtid; i < n4; i += stride) {
        float4 a = __ldg(p4 + i);
        float4 b = __ldg(t4 + i);
        unsigned u;
        u = enc_f(a.x); lmin = min(lmin, u); lmax = max(lmax, u);
        u = enc_f(a.y); lmin = min(lmin, u); lmax = max(lmax, u);
        u = enc_f(a.z); lmin = min(lmin, u); lmax = max(lmax, u);
        u = enc_f(a.w); lmin = min(lmin, u); lmax = max(lmax, u);
        u = enc_f(b.x); lmin = min(lmin, u); lmax = max(lmax, u);
        u = enc_f(b.y); lmin = min(lmin, u); lmax = max(lmax, u);
        u = enc_f(b.z); lmin = min(lmin, u); lmax = max(lmax, u);
        u = enc_f(b.w); lmin = min(lmin, u); lmax = max(lmax, u);
    }
    for (int i = (n4 << 2) + gtid; i < N; i += stride) {   // tail
        unsigned u = enc_f(__ldg(p + i));
        lmin = min(lmin, u); lmax = max(lmax, u);
        u = enc_f(__ldg(t + i));
        lmin = min(lmin, u); lmax = max(lmax, u);
    }
#pragma unroll
    for (int o = 16; o > 0; o >>= 1) {
        lmin = min(lmin, __shfl_xor_sync(0xFFFFFFFFu, lmin, o));
        lmax = max(lmax, __shfl_xor_sync(0xFFFFFFFFu, lmax, o));
    }
    __shared__ unsigned smin[8], smax[8];
    int wid = threadIdx.x >> 5;
    if ((threadIdx.x & 31) == 0) { smin[wid] = lmin; smax[wid] = lmax; }
    __syncthreads();
    if (threadIdx.x == 0) {
        unsigned m = smin[0], M = smax[0];
        int nw = blockDim.x >> 5;
        for (int w = 1; w < nw; w++) { m = min(m, smin[w]); M = max(M, smax[w]); }
        atomicMin(&g_minbits, m);   // exact, order-independent -> deterministic
        atomicMax(&g_maxbits, M);
    }
}

// Main kernel: EXACT R7 per-thread arithmetic and structure (validated,
// rel_err 1.43e-5). Single change: 4 resident blocks/SM (occupancy 24 -> 32
// warps) — the R9 profile shows no pipe saturated (fma 58%, L1 51%, issue
// 63%) at occ 30%, i.e. latency-limited.
__global__ __launch_bounds__(NT, 4)
void mi_main(const float* __restrict__ pred, const float* __restrict__ tgt,
             int N, int numTiles) {
    __shared__ float4 SH[2 * TILE * RQ];   // 36,864 B: WA then WB
    float4* WA = SH;
    float4* WB = SH + TILE * RQ;

    float minv = dec_f(g_minbits);
    float maxv = dec_f(g_maxbits);
    if (maxv <= 1.0f && minv >= 0.0f) { minv = 0.0f; maxv = 1.0f; }
    float range  = maxv - minv;
    const float inv31 = 1.0f / 31.0f;
    float sigma  = range / 31.0f;                 // /(NUM_BINS-1) * SIGMA_RATIO(=1)
    float preterm = 1.0f / ((2.0f * sigma) * sigma);
    float npre   = 0.0f - preterm;

    int t  = threadIdx.x;
    int tn = t & (TILE - 1);
    const float* src = (t < TILE) ? pred : tgt;   // threads 0..127: wa rows, 128..255: wb rows
    float4* Wrow = ((t < TILE) ? WA : WB) + tn * RQ;

    // outer-product roles
    int warp = t >> 5;            // n-subgroup: elements [warp*16, warp*16+16)
    int lane = t & 31;
    int kp   = lane >> 3;         // k-block: rows kp*8 .. kp*8+7
    int lp   = lane & 7;          // l-block: cols lp*4 .. lp*4+3
    const float4* Arow0 = WA + (warp * 16) * RQ + 2 * kp;
    const float4* Brow0 = WB + (warp * 16) * RQ + lp;

    // packed accumulators: acc2[rp][c] holds cells k = kp*8 + 2*rp + {0,1}, l = lp*4 + c
    unsigned long long acc2[4][4];
#pragma unroll
    for (int rp = 0; rp < 4; rp++)
#pragma unroll
        for (int c = 0; c < 4; c++) acc2[rp][c] = 0ull;

    for (int tile = blockIdx.x; tile < numTiles; tile += gridDim.x) {
        __syncthreads();                      // previous tile's reads complete
        int idx = tile * TILE + tn;
        float x = (idx < N) ? __ldg(src + idx) : 0.0f;

        // pass 1: compute each exp ONCE (k ascending, same S add order),
        // store unnormalized to smem, accumulate S
        float S = 0.0f;
#pragma unroll
        for (int q = 0; q < 8; q++) {
            float4 v;
            float c, d;
            c = minv + range * ((float)(4 * q + 0) * inv31); d = x - c; v.x = __expf(npre * d * d);
            c = minv + range * ((float)(4 * q + 1) * inv31); d = x - c; v.y = __expf(npre * d * d);
            c = minv + range * ((float)(4 * q + 2) * inv31); d = x - c; v.z = __expf(npre * d * d);
            c = minv + range * ((float)(4 * q + 3) * inv31); d = x - c; v.w = __expf(npre * d * d);
            S += v.x; S += v.y; S += v.z; S += v.w;
            Wrow[q] = v;
        }
        float rsc = (idx < N) ? (1.0f / S) : 0.0f;

        // pass 2: in-place scale by rsc (same multiply as R7, no recompute)
#pragma unroll
        for (int q = 0; q < 8; q++) {
            float4 v = Wrow[q];
            v.x *= rsc; v.y *= rsc; v.z *= rsc; v.w *= rsc;
            Wrow[q] = v;
        }
        __syncthreads();

        // FMA phase: 16 elements, 8x4 outer product each, as 16 fp32x2 FMAs
#pragma unroll 4
        for (int e = 0; e < 16; e++) {
            float4 a0 = Arow0[e * RQ];
            float4 a1 = Arow0[e * RQ + 1];
            float4 b  = Brow0[e * RQ];
            unsigned long long ap[4];
            ap[0] = *(const unsigned long long*)&a0.x;   // {k0,k1}
            ap[1] = *(const unsigned long long*)&a0.z;   // {k2,k3}
            ap[2] = *(const unsigned long long*)&a1.x;   // {k4,k5}
            ap[3] = *(const unsigned long long*)&a1.z;   // {k6,k7}
            unsigned long long bb[4];
            bb[0] = dup_f32(b.x);
            bb[1] = dup_f32(b.y);
            bb[2] = dup_f32(b.z);
            bb[3] = dup_f32(b.w);
#pragma unroll
            for (int rp = 0; rp < 4; rp++)
#pragma unroll
                for (int c = 0; c < 4; c++)
                    ffma2(acc2[rp][c], ap[rp], bb[c]);
        }
    }

    // combine the 8 warps' accumulators (reuse SH as float[8][1024])
    __syncthreads();
    float* sred = (float*)SH;
#pragma unroll
    for (int rp = 0; rp < 4; rp++)
#pragma unroll
        for (int c = 0; c < 4; c++) {
            unsigned lo32, hi32;
            asm("mov.b64 {%0, %1}, %2;" : "=r"(lo32), "=r"(hi32) : "l"(acc2[rp][c]));
            int k0 = kp * 8 + 2 * rp;
            int l  = lp * 4 + c;
            sred[warp * 1024 + (k0    ) * NBINS + l] = __uint_as_float(lo32);
            sred[warp * 1024 + (k0 + 1) * NBINS + l] = __uint_as_float(hi32);
        }
    __syncthreads();
    // [cell][block] layout: contiguous per-cell rows for the reduce kernel
    for (int cell = t; cell < NCELL; cell += NT) {
        float s = 0.0f;
#pragma unroll
        for (int w = 0; w < 8; w++) s += sred[w * 1024 + cell];
        g_part[cell * GBLK + blockIdx.x] = s;
    }
}

// Deterministic fp64 second-stage reduction: one BLOCK per cell (1024 blocks),
// 128 threads, coalesced contiguous loads, fixed-order pairwise tree.
__global__ void mi_reduce() {
    __shared__ double sd[128];
    int cell = blockIdx.x;
    int t = threadIdx.x;
    const float* p = g_part + cell * GBLK;
    double s = 0.0;
#pragma unroll
    for (int b = 0; b < GBLK; b += 128) {       // GBLK=592: 5 strided rounds
        if (t + b < GBLK) s += (double)p[t + b];
    }
    sd[t] = s;
    __syncthreads();
#pragma unroll
    for (int o = 64; o > 0; o >>= 1) {
        if (t < o) sd[t] = sd[t] + sd[t + o];   // fixed tree order -> deterministic
        __syncthreads();
    }
    if (t == 0) g_pab[cell] = sd[0];
}

// epilogue: pa/pb as row/col sums, MI in fp64, write -mi
__global__ void mi_final(float* __restrict__ out, int N) {
    __shared__ double pa[NBINS], pb[NBINS], red[32];
    int t = threadIdx.x;
    double invN = 1.0 / (double)N;
    if (t < 32) {
        double s = 0.0;
        for (int l = 0; l < NBINS; l++) s += g_pab[t * NBINS + l];
        pa[t] = s * invN;
    } else if (t < 64) {
        int l = t - 32;
        double s = 0.0;
        for (int k = 0; k < NBINS; k++) s += g_pab[k * NBINS + l];
        pb[l] = s * invN;
    }
    __syncthreads();

    int k = t >> 5, l = t & 31;                 // t in [0,1024): one cell per thread
    double pab  = g_pab[t] * invN;
    double papb = pa[k] * pb[l];
    double term = pab * log((pab + 1e-7) / (papb + 1e-7) + 1e-7);

#pragma unroll
    for (int o = 16; o > 0; o >>= 1)
        term += __shfl_xor_sync(0xFFFFFFFFu, term, o);
    if (l == 0) red[k] = term;                  // k == warp id (32 warps)
    __syncthreads();
    if (t < 32) {
        double v = red[t];
#pragma unroll
        for (int o = 16; o > 0; o >>= 1)
            v += __shfl_xor_sync(0xFFFFFFFFu, v, o);
        if (t == 0) *out = (float)(-v);
    }
}

extern "C" void kernel_launch(void* const* d_in, const int* in_sizes, int n_in,
                              void* d_out, int out_size) {
    const float* pred = (const float*)d_in[0];
    const float* tgt  = (const float*)d_in[1];
    int N = in_sizes[0];
    int numTiles = (N + TILE - 1) / TILE;

    mi_init<<<1, 1>>>();
    mi_minmax<<<1184, 256>>>(pred, tgt, N);
    mi_probe<<<1, 1>>>();   // keeps mi_main at ncu capture slot (launch idx 5)
    mi_main<<<GBLK, NT>>>(pred, tgt, N, numTiles);
    mi_reduce<<<NCELL, 128>>>();
    mi_final<<<1, 1024>>>((float*)d_out, N);
}

// round 11
// speedup vs baseline: 1.0784x; 1.0784x over previous
#include <cuda_runtime.h>
#include <cuda_bf16.h>
#include <math.h>

#define NBINS 32
#define TILE  128
#define NT    256
#define GBLK  444          // 148 SMs * 3 resident blocks
#define RQ    9            // smem row stride in float4 (8 data quads + 1 pad)
#define NCELL (NBINS * NBINS)

// ---------------- scratch (no allocations allowed) ----------------
__device__ unsigned g_minbits;
__device__ unsigned g_maxbits;
__device__ int      g_arrived;              // reduce->final handoff counter
__device__ float    g_part[NCELL * GBLK];   // [cell][block] fp32 partials (~1.8 MB)
__device__ double   g_pab[NCELL];           // fp64 joint histogram sums

// order-preserving encoding so uint atomicMin/Max give exact float min/max
__device__ __forceinline__ unsigned enc_f(float v) {
    unsigned u = __float_as_uint(v);
    return (u & 0x80000000u) ? ~u : (u | 0x80000000u);
}
__device__ __forceinline__ float dec_f(unsigned u) {
    return (u & 0x80000000u) ? __uint_as_float(u & 0x7FFFFFFFu)
                             : __uint_as_float(~u);
}

// packed fp32x2 FMA: each half is an exact IEEE fp32 FMA (bit-identical to fmaf)
__device__ __forceinline__ void ffma2(unsigned long long& d,
                                      unsigned long long a,
                                      unsigned long long b) {
    asm("fma.rn.f32x2 %0, %1, %2, %0;" : "+l"(d) : "l"(a), "l"(b));
}
__device__ __forceinline__ unsigned long long dup_f32(float v) {
    unsigned long long r;
    asm("mov.b64 %0, {%1, %1};" : "=l"(r) : "r"(__float_as_uint(v)));
    return r;
}

__global__ void mi_init() {
    g_minbits = 0xFFFFFFFFu;
    g_maxbits = 0u;
    g_arrived = 0;
}

// no-op probe: keeps mi_main at global launch index 5 so ncu (-s 5 -c 1)
// captures the hot kernel instead of the reduce.
__global__ void mi_probe() {}

__global__ void mi_minmax(const float* __restrict__ p,
                          const float* __restrict__ t, int N) {
    unsigned lmin = 0xFFFFFFFFu, lmax = 0u;
    int stride = gridDim.x * blockDim.x;
    int gtid = blockIdx.x * blockDim.x + threadIdx.x;
    int n4 = N >> 2;
    const float4* p4 = (const float4*)p;
    const float4* t4 = (const float4*)t;
    for (int i = gtid; i < n4; i += stride) {
        float4 a = __ldg(p4 + i);
        float4 b = __ldg(t4 + i);
        unsigned u;
        u = enc_f(a.x); lmin = min(lmin, u); lmax = max(lmax, u);
        u = enc_f(a.y); lmin = min(lmin, u); lmax = max(lmax, u);
        u = enc_f(a.z); lmin = min(lmin, u); lmax = max(lmax, u);
        u = enc_f(a.w); lmin = min(lmin, u); lmax = max(lmax, u);
        u = enc_f(b.x); lmin = min(lmin, u); lmax = max(lmax, u);
        u = enc_f(b.y); lmin = min(lmin, u); lmax = max(lmax, u);
        u = enc_f(b.z); lmin = min(lmin, u); lmax = max(lmax, u);
        u = enc_f(b.w); lmin = min(lmin, u); lmax = max(lmax, u);
    }
    for (int i = (n4 << 2) + gtid; i < N; i += stride) {   // tail
        unsigned u = enc_f(__ldg(p + i));
        lmin = min(lmin, u); lmax = max(lmax, u);
        u = enc_f(__ldg(t + i));
        lmin = min(lmin, u); lmax = max(lmax, u);
    }
#pragma unroll
    for (int o = 16; o > 0; o >>= 1) {
        lmin = min(lmin, __shfl_xor_sync(0xFFFFFFFFu, lmin, o));
        lmax = max(lmax, __shfl_xor_sync(0xFFFFFFFFu, lmax, o));
    }
    __shared__ unsigned smin[8], smax[8];
    int wid = threadIdx.x >> 5;
    if ((threadIdx.x & 31) == 0) { smin[wid] = lmin; smax[wid] = lmax; }
    __syncthreads();
    if (threadIdx.x == 0) {
        unsigned m = smin[0], M = smax[0];
        int nw = blockDim.x >> 5;
        for (int w = 1; w < nw; w++) { m = min(m, smin[w]); M = max(M, smax[w]); }
        atomicMin(&g_minbits, m);   // exact, order-independent -> deterministic
        atomicMax(&g_maxbits, M);
    }
}

// Main kernel: EXACT R9 per-thread arithmetic (validated, rel_err 1.43e-5),
// launch_bounds(256,3) (regs free -> stable weight-chain compilation).
// Single change: bin centers c_k hoisted out of the tile loop — computed ONCE
// with the identical expression into smem (bit-identical values), replacing
// 32 per-tile FFMAs with 8 LDS.128 in the fma-bound weight phase.
__global__ __launch_bounds__(NT, 3)
void mi_main(const float* __restrict__ pred, const float* __restrict__ tgt,
             int N, int numTiles) {
    __shared__ float4 SH[2 * TILE * RQ];   // 36,864 B: WA then WB
    __shared__ float4 CB[8];               // 32 bin centers (hoisted)
    float4* WA = SH;
    float4* WB = SH + TILE * RQ;

    float minv = dec_f(g_minbits);
    float maxv = dec_f(g_maxbits);
    if (maxv <= 1.0f && minv >= 0.0f) { minv = 0.0f; maxv = 1.0f; }
    float range  = maxv - minv;
    const float inv31 = 1.0f / 31.0f;
    float sigma  = range / 31.0f;                 // /(NUM_BINS-1) * SIGMA_RATIO(=1)
    float preterm = 1.0f / ((2.0f * sigma) * sigma);
    float npre   = 0.0f - preterm;

    int t  = threadIdx.x;
    // bin centers: SAME expression as the original per-tile computation ->
    // bit-identical values, evaluated once per block instead of per tile.
    if (t < 8) {
        float4 cq;
        cq.x = minv + range * ((float)(4 * t + 0) * inv31);
        cq.y = minv + range * ((float)(4 * t + 1) * inv31);
        cq.z = minv + range * ((float)(4 * t + 2) * inv31);
        cq.w = minv + range * ((float)(4 * t + 3) * inv31);
        CB[t] = cq;
    }
    // (visible after the first in-loop __syncthreads below)

    int tn = t & (TILE - 1);
    const float* src = (t < TILE) ? pred : tgt;   // threads 0..127: wa rows, 128..255: wb rows
    float4* Wrow = ((t < TILE) ? WA : WB) + tn * RQ;

    // outer-product roles
    int warp = t >> 5;            // n-subgroup: elements [warp*16, warp*16+16)
    int lane = t & 31;
    int kp   = lane >> 3;         // k-block: rows kp*8 .. kp*8+7
    int lp   = lane & 7;          // l-block: cols lp*4 .. lp*4+3
    const float4* Arow0 = WA + (warp * 16) * RQ + 2 * kp;
    const float4* Brow0 = WB + (warp * 16) * RQ + lp;

    // packed accumulators: acc2[rp][c] holds cells k = kp*8 + 2*rp + {0,1}, l = lp*4 + c
    unsigned long long acc2[4][4];
#pragma unroll
    for (int rp = 0; rp < 4; rp++)
#pragma unroll
        for (int c = 0; c < 4; c++) acc2[rp][c] = 0ull;

    for (int tile = blockIdx.x; tile < numTiles; tile += gridDim.x) {
        __syncthreads();                      // prev reads done; CB visible (1st iter)
        int idx = tile * TILE + tn;
        float x = (idx < N) ? __ldg(src + idx) : 0.0f;

        // pass 1: compute each exp ONCE (k ascending, same S add order),
        // store unnormalized to smem, accumulate S
        float S = 0.0f;
#pragma unroll
        for (int q = 0; q < 8; q++) {
            float4 cq = CB[q];
            float4 v;
            float d;
            d = x - cq.x; v.x = __expf(npre * d * d);
            d = x - cq.y; v.y = __expf(npre * d * d);
            d = x - cq.z; v.z = __expf(npre * d * d);
            d = x - cq.w; v.w = __expf(npre * d * d);
            S += v.x; S += v.y; S += v.z; S += v.w;
            Wrow[q] = v;
        }
        float rsc = (idx < N) ? (1.0f / S) : 0.0f;

        // pass 2: in-place scale by rsc (same multiply, no recompute)
#pragma unroll
        for (int q = 0; q < 8; q++) {
            float4 v = Wrow[q];
            v.x *= rsc; v.y *= rsc; v.z *= rsc; v.w *= rsc;
            Wrow[q] = v;
        }
        __syncthreads();

        // FMA phase: 16 elements, 8x4 outer product each, as 16 fp32x2 FMAs
#pragma unroll 4
        for (int e = 0; e < 16; e++) {
            float4 a0 = Arow0[e * RQ];
            float4 a1 = Arow0[e * RQ + 1];
            float4 b  = Brow0[e * RQ];
            unsigned long long ap[4];
            ap[0] = *(const unsigned long long*)&a0.x;   // {k0,k1}
            ap[1] = *(const unsigned long long*)&a0.z;   // {k2,k3}
            ap[2] = *(const unsigned long long*)&a1.x;   // {k4,k5}
            ap[3] = *(const unsigned long long*)&a1.z;   // {k6,k7}
            unsigned long long bb[4];
            bb[0] = dup_f32(b.x);
            bb[1] = dup_f32(b.y);
            bb[2] = dup_f32(b.z);
            bb[3] = dup_f32(b.w);
#pragma unroll
            for (int rp = 0; rp < 4; rp++)
#pragma unroll
                for (int c = 0; c < 4; c++)
                    ffma2(acc2[rp][c], ap[rp], bb[c]);
        }
    }

    // combine the 8 warps' accumulators (reuse SH as float[8][1024])
    __syncthreads();
    float* sred = (float*)SH;
#pragma unroll
    for (int rp = 0; rp < 4; rp++)
#pragma unroll
        for (int c = 0; c < 4; c++) {
            unsigned lo32, hi32;
            asm("mov.b64 {%0, %1}, %2;" : "=r"(lo32), "=r"(hi32) : "l"(acc2[rp][c]));
            int k0 = kp * 8 + 2 * rp;
            int l  = lp * 4 + c;
            sred[warp * 1024 + (k0    ) * NBINS + l] = __uint_as_float(lo32);
            sred[warp * 1024 + (k0 + 1) * NBINS + l] = __uint_as_float(hi32);
        }
    __syncthreads();
    // [cell][block] layout: contiguous per-cell rows for the reduce kernel
    for (int cell = t; cell < NCELL; cell += NT) {
        float s = 0.0f;
#pragma unroll
        for (int w = 0; w < 8; w++) s += sred[w * 1024 + cell];
        g_part[cell * GBLK + blockIdx.x] = s;
    }
}

// Fused second-stage reduction + MI epilogue. Reduction identical to R9
// (one block per cell, coalesced loads, fixed-order fp64 tree). The LAST
// arriving block (threadfence + counter; value is block-order independent)
// computes pa/pb and the MI sum and writes -mi.
__global__ void mi_reduce_final(float* __restrict__ out, int N) {
    __shared__ double sd[128];
    __shared__ double pa[NBINS], pb[NBINS];
    __shared__ int lastFlag;
    int cell = blockIdx.x;
    int t = threadIdx.x;
    const float* p = g_part + cell * GBLK;
    double s = 0.0;
    s += (double)p[t];                          // GBLK=444 > 128: t always valid
    s += (double)p[t + 128];
    s += (double)p[t + 256];
    if (t + 384 < GBLK) s += (double)p[t + 384];
    sd[t] = s;
    __syncthreads();
#pragma unroll
    for (int o = 64; o > 0; o >>= 1) {
        if (t < o) sd[t] = sd[t] + sd[t + o];   // fixed tree order -> deterministic
        __syncthreads();
    }
    if (t == 0) {
        g_pab[cell] = sd[0];
        __threadfence();
        int n = atomicAdd(&g_arrived, 1);
        lastFlag = (n == NCELL - 1) ? 1 : 0;
        if (lastFlag) g_arrived = 0;            // re-arm for next graph replay
    }
    __syncthreads();
    if (!lastFlag) return;
    __threadfence();                            // all g_pab writes visible

    // ---- epilogue (128 threads) ----
    double invN = 1.0 / (double)N;
    if (t < 32) {
        double sr = 0.0;
        for (int l = 0; l < NBINS; l++) sr += g_pab[t * NBINS + l];
        pa[t] = sr * invN;
    } else if (t < 64) {
        int l = t - 32;
        double sc = 0.0;
        for (int k = 0; k < NBINS; k++) sc += g_pab[k * NBINS + l];
        pb[l] = sc * invN;
    }
    __syncthreads();

    double acc = 0.0;
#pragma unroll
    for (int i = 0; i < 8; i++) {               // cells t, t+128, ... (fixed order)
        int c2 = t + i * 128;
        int k = c2 >> 5, l = c2 & 31;
        double pab  = g_pab[c2] * invN;
        double papb = pa[k] * pb[l];
        acc += pab * log((pab + 1e-7) / (papb + 1e-7) + 1e-7);
    }
    sd[t] = acc;
    __syncthreads();
#pragma unroll
    for (int o = 64; o > 0; o >>= 1) {
        if (t < o) sd[t] = sd[t] + sd[t + o];   // fixed tree -> deterministic
        __syncthreads();
    }
    if (t == 0) *out = (float)(-sd[0]);
}

extern "C" void kernel_launch(void* const* d_in, const int* in_sizes, int n_in,
                              void* d_out, int out_size) {
    const float* pred = (const float*)d_in[0];
    const float* tgt  = (const float*)d_in[1];
    int N = in_sizes[0];
    int numTiles = (N + TILE - 1) / TILE;

    mi_init<<<1, 1>>>();
    mi_minmax<<<1184, 256>>>(pred, tgt, N);
    mi_probe<<<1, 1>>>();   // keeps mi_main at ncu capture slot (launch idx 5)
    mi_main<<<GBLK, NT>>>(pred, tgt, N, numTiles);
    mi_reduce_final<<<NCELL, 128>>>((float*)d_out, N);
}